// round 16
// baseline (speedup 1.0000x reference)
#include <cuda_runtime.h>
#include <cuda_bf16.h>
#include <cstdint>

// Fragment-order packed weights (uint2 per lane per tile), hi/lo bf16 splits.
// g_pb[blk][split][q(16)][j(4)][lane(32)][w(2)]  : colw*alpha, B-frag of D1 GEMM
// g_pc[blk][split][s(2)][n(32)][lane(32)][w(2)]  : roww,      B-frag of D2 GEMM
__device__ uint32_t g_pb[3][2][16][4][32][2];
__device__ uint32_t g_pc[3][2][2][32][32][2];

__device__ __forceinline__ float tanh_fast(float v) {
    float e = __expf(2.0f * v);
    return 1.0f - __fdividef(2.0f, e + 1.0f);
}

// d[0..3] += A(m16k16 bf16) * B(k16n8 bf16)   (f32 accumulate)
__device__ __forceinline__ void mma16816(float* d, const uint32_t* a, uint2 b) {
    asm volatile(
        "mma.sync.aligned.m16n8k16.row.col.f32.bf16.bf16.f32 "
        "{%0,%1,%2,%3}, {%4,%5,%6,%7}, {%8,%9}, {%0,%1,%2,%3};"
        : "+f"(d[0]), "+f"(d[1]), "+f"(d[2]), "+f"(d[3])
        : "r"(a[0]), "r"(a[1]), "r"(a[2]), "r"(a[3]), "r"(b.x), "r"(b.y));
}

// hi/lo bf16x2 split of (v0 -> low half, v1 -> high half)
__device__ __forceinline__ void split2(float v0, float v1, uint32_t& hi, uint32_t& lo) {
    uint32_t h;
    asm("cvt.rn.bf16x2.f32 %0, %1, %2;" : "=r"(h) : "f"(v1), "f"(v0));
    const float e0 = v0 - __uint_as_float(h << 16);
    const float e1 = v1 - __uint_as_float(h & 0xFFFF0000u);
    uint32_t l;
    asm("cvt.rn.bf16x2.f32 %0, %1, %2;" : "=r"(l) : "f"(e1), "f"(e0));
    hi = h; lo = l;
}

__device__ __forceinline__ uint32_t bf16x2_of(float v0, float v1, int split) {
    __nv_bfloat16 h0 = __float2bfloat16_rn(v0), h1 = __float2bfloat16_rn(v1);
    if (split) {
        h0 = __float2bfloat16_rn(v0 - __bfloat162float(h0));
        h1 = __float2bfloat16_rn(v1 - __bfloat162float(h1));
    }
    uint16_t b0 = __bfloat16_as_ushort(h0), b1 = __bfloat16_as_ushort(h1);
    return (uint32_t)b0 | ((uint32_t)b1 << 16);
}

__global__ void pack_kernel(const float* __restrict__ col0, const float* __restrict__ col1,
                            const float* __restrict__ col2, const float* __restrict__ row0,
                            const float* __restrict__ row1, const float* __restrict__ row2,
                            const float* __restrict__ al0, const float* __restrict__ al1,
                            const float* __restrict__ al2)
{
    int idx = blockIdx.x * blockDim.x + threadIdx.x;
    const int NPB = 3 * 2 * 16 * 4 * 32 * 2;   // 24576
    if (idx < NPB) {
        const int w = idx & 1, lane = (idx >> 1) & 31, j = (idx >> 6) & 3;
        const int q = (idx >> 8) & 15, split = (idx >> 12) & 1, b = idx >> 13;
        const int g = lane >> 2, t = lane & 3;
        const int k0 = 16 * q + 2 * t + 8 * w;
        const int n  = 8 * j + g;
        const float* c = (b == 0) ? col0 : (b == 1) ? col1 : col2;
        const float* a = (b == 0) ? al0 : (b == 1) ? al1 : al2;
        const float av = a[n];
        g_pb[b][split][q][j][lane][w] =
            bf16x2_of(c[k0 * 32 + n] * av, c[(k0 + 1) * 32 + n] * av, split);
        return;
    }
    idx -= NPB;
    if (idx < 3 * 2 * 2 * 32 * 32 * 2) {       // 24576
        const int w = idx & 1, lane = (idx >> 1) & 31, n = (idx >> 6) & 31;
        const int s = (idx >> 11) & 1, split = (idx >> 12) & 1, b = idx >> 13;
        const int g = lane >> 2, t = lane & 3;
        const int k0 = 16 * s + 2 * t + 8 * w;
        const int jj = 8 * n + g;
        const float* rw = (b == 0) ? row0 : (b == 1) ? row1 : row2;
        g_pc[b][split][s][n][lane][w] =
            bf16x2_of(rw[jj * 32 + k0], rw[jj * 32 + k0 + 1], split);
    }
}

__global__ void __launch_bounds__(128, 2) pinn_kernel(
    const float* __restrict__ gx, const float* __restrict__ gt,
    const float* __restrict__ start_w, const float* __restrict__ start_b,
    const float* __restrict__ end_w, const float* __restrict__ end_b,
    float* __restrict__ out)
{
    const int tid  = threadIdx.x;
    const int warp = tid >> 5;
    const int lane = tid & 31;
    const int g    = lane >> 2;     // row-in-tile group
    const int t    = lane & 3;      // col group
    const int r0   = blockIdx.x * 64 + warp * 16 + g;   // this thread's two rows
    const int r1   = r0 + 8;

    // ---- Phase A: h frags = tanh([x,t]@start_w.T + start_b), hi/lo bf16 ----
    uint32_t ahi[64], alo[64];
    {
        const float x0 = __ldg(gx + r0), x1 = __ldg(gx + r1);
        const float t0 = __ldg(gt + r0), t1 = __ldg(gt + r1);
        #pragma unroll
        for (int q = 0; q < 16; q++) {
            const int c0 = 16 * q + 2 * t;
            float h0[4], h1[4];   // (row r0 / r1) x cols {c0, c0+1, c0+8, c0+9}
            #pragma unroll
            for (int e = 0; e < 4; e++) {
                const int j  = c0 + (e >> 1) * 8 + (e & 1);
                const float w0 = __ldg(start_w + 2 * j);
                const float w1 = __ldg(start_w + 2 * j + 1);
                const float bb = __ldg(start_b + j);
                h0[e] = tanh_fast(fmaf(x0, w0, fmaf(t0, w1, bb)));
                h1[e] = tanh_fast(fmaf(x1, w0, fmaf(t1, w1, bb)));
            }
            split2(h0[0], h0[1], ahi[q * 4 + 0], alo[q * 4 + 0]);
            split2(h1[0], h1[1], ahi[q * 4 + 1], alo[q * 4 + 1]);
            split2(h0[2], h0[3], ahi[q * 4 + 2], alo[q * 4 + 2]);
            split2(h1[2], h1[3], ahi[q * 4 + 3], alo[q * 4 + 3]);
        }
    }

    float s0 = 0.0f, s1 = 0.0f;

    #pragma unroll 1
    for (int blk = 0; blk < 3; blk++) {
        const uint2* pbh = (const uint2*)&g_pb[blk][0][0][0][0][0];
        const uint2* pbl = (const uint2*)&g_pb[blk][1][0][0][0][0];
        const uint2* pch = (const uint2*)&g_pc[blk][0][0][0][0][0];
        const uint2* pcl = (const uint2*)&g_pc[blk][1][0][0][0][0];

        // ---- GEMM 1: D1[16,32] = h @ (col*alpha); 3 precision passes, each
        //      with its OWN accumulator set -> 12 independent mma chains
        //      (vs 4 chains x 48-deep when all passes share one set). ----
        float dhh[16], dlh[16], dhl[16];
        #pragma unroll
        for (int i = 0; i < 16; i++) { dhh[i] = 0.0f; dlh[i] = 0.0f; dhl[i] = 0.0f; }
        #pragma unroll
        for (int q = 0; q < 16; q++) {
            #pragma unroll
            for (int j = 0; j < 4; j++) {
                const uint2 bh = __ldg(&pbh[(q * 4 + j) * 32 + lane]);
                const uint2 bl = __ldg(&pbl[(q * 4 + j) * 32 + lane]);
                mma16816(&dhh[j * 4], &ahi[q * 4], bh);
                mma16816(&dlh[j * 4], &alo[q * 4], bh);
                mma16816(&dhl[j * 4], &ahi[q * 4], bl);
            }
        }
        float d1[16];
        #pragma unroll
        for (int i = 0; i < 16; i++) d1[i] = dhh[i] + dlh[i] + dhl[i];

        // ---- u = D1 (linear), repack to A frags (m16k32) hi/lo ----
        uint32_t uhi[8], ulo[8];
        #pragma unroll
        for (int s = 0; s < 2; s++) {
            split2(d1[(2*s)*4 + 0], d1[(2*s)*4 + 1], uhi[s*4 + 0], ulo[s*4 + 0]);
            split2(d1[(2*s)*4 + 2], d1[(2*s)*4 + 3], uhi[s*4 + 1], ulo[s*4 + 1]);
            split2(d1[(2*s+1)*4 + 0], d1[(2*s+1)*4 + 1], uhi[s*4 + 2], ulo[s*4 + 2]);
            split2(d1[(2*s+1)*4 + 2], d1[(2*s+1)*4 + 3], uhi[s*4 + 3], ulo[s*4 + 3]);
        }

        // ---- GEMM 2: D2[16,256] = u @ row^T; full 128-acc version (32
        //      independent chains -> max tensor-pipe ILP, as in R14) ----
        float d2[128];
        #pragma unroll
        for (int i = 0; i < 128; i++) d2[i] = 0.0f;
        #pragma unroll
        for (int n = 0; n < 32; n++) {
            #pragma unroll
            for (int s = 0; s < 2; s++) {
                const uint2 bh = __ldg(&pch[(s * 32 + n) * 32 + lane]);
                const uint2 bl = __ldg(&pcl[(s * 32 + n) * 32 + lane]);
                mma16816(&d2[n * 4], &uhi[s * 4], bh);
                mma16816(&d2[n * 4], &ulo[s * 4], bh);
                mma16816(&d2[n * 4], &uhi[s * 4], bl);
            }
        }

        if (blk < 2) {
            // ---- h' = tanh(D2): D-frags ARE next A-frags (in place) ----
            #pragma unroll
            for (int q = 0; q < 16; q++) {
                split2(tanh_fast(d2[(2*q)*4 + 0]), tanh_fast(d2[(2*q)*4 + 1]),
                       ahi[q*4 + 0], alo[q*4 + 0]);
                split2(tanh_fast(d2[(2*q)*4 + 2]), tanh_fast(d2[(2*q)*4 + 3]),
                       ahi[q*4 + 1], alo[q*4 + 1]);
                split2(tanh_fast(d2[(2*q+1)*4 + 0]), tanh_fast(d2[(2*q+1)*4 + 1]),
                       ahi[q*4 + 2], alo[q*4 + 2]);
                split2(tanh_fast(d2[(2*q+1)*4 + 2]), tanh_fast(d2[(2*q+1)*4 + 3]),
                       ahi[q*4 + 3], alo[q*4 + 3]);
            }
        } else {
            // ---- fused Phase D: dot with end_w ----
            #pragma unroll
            for (int n = 0; n < 32; n++) {
                const int c0 = 8 * n + 2 * t;
                const float e0 = __ldg(end_w + c0), e1 = __ldg(end_w + c0 + 1);
                s0 = fmaf(tanh_fast(d2[n*4 + 0]), e0, s0);
                s0 = fmaf(tanh_fast(d2[n*4 + 1]), e1, s0);
                s1 = fmaf(tanh_fast(d2[n*4 + 2]), e0, s1);
                s1 = fmaf(tanh_fast(d2[n*4 + 3]), e1, s1);
            }
        }
    }

    // reduce across the 4 lanes of each row group
    s0 += __shfl_xor_sync(0xffffffffu, s0, 1);
    s0 += __shfl_xor_sync(0xffffffffu, s0, 2);
    s1 += __shfl_xor_sync(0xffffffffu, s1, 1);
    s1 += __shfl_xor_sync(0xffffffffu, s1, 2);
    if (t == 0) {
        const float eb = __ldg(end_b);
        out[r0] = s0 + eb;
        out[r1] = s1 + eb;
    }
}

extern "C" void kernel_launch(void* const* d_in, const int* in_sizes, int n_in,
                              void* d_out, int out_size) {
    const float* x  = (const float*)d_in[0];
    const float* t  = (const float*)d_in[1];
    const float* sw = (const float*)d_in[2];
    const float* sb = (const float*)d_in[3];
    const float* ew = (const float*)d_in[4];
    const float* eb = (const float*)d_in[5];
    const float* c0 = (const float*)d_in[6];
    const float* c1 = (const float*)d_in[7];
    const float* c2 = (const float*)d_in[8];
    const float* r0 = (const float*)d_in[9];
    const float* r1 = (const float*)d_in[10];
    const float* r2 = (const float*)d_in[11];
    const float* a0 = (const float*)d_in[12];
    const float* a1 = (const float*)d_in[13];
    const float* a2 = (const float*)d_in[14];
    float* out = (float*)d_out;
    const int N = in_sizes[0];

    pack_kernel<<<(49152 + 255) / 256, 256>>>(c0, c1, c2, r0, r1, r2, a0, a1, a2);
    pinn_kernel<<<N / 64, 128>>>(x, t, sw, sb, ew, eb, out);
}

// round 17
// speedup vs baseline: 1.2178x; 1.2178x over previous
#include <cuda_runtime.h>
#include <cuda_bf16.h>
#include <cstdint>

// B-fragments with hi/lo splits ADJACENT: one uint4 = {hi.w0, hi.w1, lo.w0, lo.w1}
// g_pb4[blk][site = q*4+j][lane] : colw*alpha  (B of GEMM1)
// g_pc4[blk][site = s*32+n][lane] : roww       (B of GEMM2)
__device__ uint4 g_pb4[3][64][32];
__device__ uint4 g_pc4[3][64][32];

__device__ __forceinline__ float tanh_fast(float v) {
    float e = __expf(2.0f * v);
    return 1.0f - __fdividef(2.0f, e + 1.0f);
}

// d[0..3] += A(m16k16 bf16) * B(k16n8 bf16)   (f32 accumulate)
__device__ __forceinline__ void mma16816(float* d, const uint32_t* a, uint32_t b0, uint32_t b1) {
    asm volatile(
        "mma.sync.aligned.m16n8k16.row.col.f32.bf16.bf16.f32 "
        "{%0,%1,%2,%3}, {%4,%5,%6,%7}, {%8,%9}, {%0,%1,%2,%3};"
        : "+f"(d[0]), "+f"(d[1]), "+f"(d[2]), "+f"(d[3])
        : "r"(a[0]), "r"(a[1]), "r"(a[2]), "r"(a[3]), "r"(b0), "r"(b1));
}

// hi/lo bf16x2 split of (v0 -> low half, v1 -> high half)
__device__ __forceinline__ void split2(float v0, float v1, uint32_t& hi, uint32_t& lo) {
    uint32_t h;
    asm("cvt.rn.bf16x2.f32 %0, %1, %2;" : "=r"(h) : "f"(v1), "f"(v0));
    const float e0 = v0 - __uint_as_float(h << 16);
    const float e1 = v1 - __uint_as_float(h & 0xFFFF0000u);
    uint32_t l;
    asm("cvt.rn.bf16x2.f32 %0, %1, %2;" : "=r"(l) : "f"(e1), "f"(e0));
    hi = h; lo = l;
}

__device__ __forceinline__ uint32_t bf16x2_of(float v0, float v1, int split) {
    __nv_bfloat16 h0 = __float2bfloat16_rn(v0), h1 = __float2bfloat16_rn(v1);
    if (split) {
        h0 = __float2bfloat16_rn(v0 - __bfloat162float(h0));
        h1 = __float2bfloat16_rn(v1 - __bfloat162float(h1));
    }
    uint16_t b0 = __bfloat16_as_ushort(h0), b1 = __bfloat16_as_ushort(h1);
    return (uint32_t)b0 | ((uint32_t)b1 << 16);
}

__global__ void pack_kernel(const float* __restrict__ col0, const float* __restrict__ col1,
                            const float* __restrict__ col2, const float* __restrict__ row0,
                            const float* __restrict__ row1, const float* __restrict__ row2,
                            const float* __restrict__ al0, const float* __restrict__ al1,
                            const float* __restrict__ al2)
{
    int idx = blockIdx.x * blockDim.x + threadIdx.x;     // 2 * 3 * 64 * 32 total
    const int half = 3 * 64 * 32;                        // 6144
    const int g_l  = (idx % 32) >> 2;                    // placeholder (recomputed below)
    (void)g_l;
    if (idx < half) {
        const int b = idx / 2048, site = (idx / 32) % 64, lane = idx % 32;
        const int q = site >> 2, j = site & 3;
        const int g = lane >> 2, t = lane & 3;
        const int k0 = 16 * q + 2 * t;
        const int n  = 8 * j + g;
        const float* c = (b == 0) ? col0 : (b == 1) ? col1 : col2;
        const float* a = (b == 0) ? al0 : (b == 1) ? al1 : al2;
        const float av = a[n];
        uint4 v;
        v.x = bf16x2_of(c[k0 * 32 + n] * av,       c[(k0 + 1) * 32 + n] * av, 0);
        v.y = bf16x2_of(c[(k0 + 8) * 32 + n] * av, c[(k0 + 9) * 32 + n] * av, 0);
        v.z = bf16x2_of(c[k0 * 32 + n] * av,       c[(k0 + 1) * 32 + n] * av, 1);
        v.w = bf16x2_of(c[(k0 + 8) * 32 + n] * av, c[(k0 + 9) * 32 + n] * av, 1);
        g_pb4[b][site][lane] = v;
        return;
    }
    idx -= half;
    if (idx < half) {
        const int b = idx / 2048, site = (idx / 32) % 64, lane = idx % 32;
        const int s = site >> 5, n = site & 31;
        const int g = lane >> 2, t = lane & 3;
        const int k0 = 16 * s + 2 * t;
        const int jj = 8 * n + g;
        const float* rw = (b == 0) ? row0 : (b == 1) ? row1 : row2;
        uint4 v;
        v.x = bf16x2_of(rw[jj * 32 + k0],     rw[jj * 32 + k0 + 1], 0);
        v.y = bf16x2_of(rw[jj * 32 + k0 + 8], rw[jj * 32 + k0 + 9], 0);
        v.z = bf16x2_of(rw[jj * 32 + k0],     rw[jj * 32 + k0 + 1], 1);
        v.w = bf16x2_of(rw[jj * 32 + k0 + 8], rw[jj * 32 + k0 + 9], 1);
        g_pc4[b][site][lane] = v;
    }
}

__global__ void __launch_bounds__(128, 3) pinn_kernel(
    const float* __restrict__ gx, const float* __restrict__ gt,
    const float* __restrict__ start_w, const float* __restrict__ start_b,
    const float* __restrict__ end_w, const float* __restrict__ end_b,
    float* __restrict__ out)
{
    // per-thread-private lo A-frags in SMEM: [q][tid] uint4, coalesced, no barriers
    __shared__ uint4 s_alo[16 * 128];

    const int tid  = threadIdx.x;
    const int warp = tid >> 5;
    const int lane = tid & 31;
    const int g    = lane >> 2;     // row-in-tile group
    const int t    = lane & 3;      // col group
    const int r0   = blockIdx.x * 64 + warp * 16 + g;   // this thread's two rows
    const int r1   = r0 + 8;

    // ---- Phase A: h frags = tanh([x,t]@start_w.T + start_b); hi in regs, lo in smem
    uint32_t ahi[64];
    {
        const float x0 = __ldg(gx + r0), x1 = __ldg(gx + r1);
        const float t0 = __ldg(gt + r0), t1 = __ldg(gt + r1);
        #pragma unroll
        for (int q = 0; q < 16; q++) {
            const int c0 = 16 * q + 2 * t;
            float h0[4], h1[4];   // (row r0 / r1) x cols {c0, c0+1, c0+8, c0+9}
            #pragma unroll
            for (int e = 0; e < 4; e++) {
                const int j  = c0 + (e >> 1) * 8 + (e & 1);
                const float w0 = __ldg(start_w + 2 * j);
                const float w1 = __ldg(start_w + 2 * j + 1);
                const float bb = __ldg(start_b + j);
                h0[e] = tanh_fast(fmaf(x0, w0, fmaf(t0, w1, bb)));
                h1[e] = tanh_fast(fmaf(x1, w0, fmaf(t1, w1, bb)));
            }
            uint4 lo;
            split2(h0[0], h0[1], ahi[q * 4 + 0], lo.x);
            split2(h1[0], h1[1], ahi[q * 4 + 1], lo.y);
            split2(h0[2], h0[3], ahi[q * 4 + 2], lo.z);
            split2(h1[2], h1[3], ahi[q * 4 + 3], lo.w);
            s_alo[q * 128 + tid] = lo;
        }
    }

    float s0 = 0.0f, s1 = 0.0f;

    #pragma unroll 1
    for (int blk = 0; blk < 3; blk++) {
        const uint4* pb = &g_pb4[blk][0][0];
        const uint4* pc = &g_pc4[blk][0][0];

        // ---- GEMM 1: D1[16,32] = h @ (col*alpha); 3 precision passes ----
        float d1[16];
        #pragma unroll
        for (int i = 0; i < 16; i++) d1[i] = 0.0f;
        #pragma unroll
        for (int q = 0; q < 16; q++) {
            const uint4 lov = s_alo[q * 128 + tid];
            uint32_t aloq[4] = {lov.x, lov.y, lov.z, lov.w};
            #pragma unroll
            for (int j = 0; j < 4; j++) {
                const uint4 bb = __ldg(&pb[(q * 4 + j) * 32 + lane]);  // one LDG.128
                mma16816(&d1[j * 4], &ahi[q * 4], bb.x, bb.y);
                mma16816(&d1[j * 4], aloq,        bb.x, bb.y);
                mma16816(&d1[j * 4], &ahi[q * 4], bb.z, bb.w);
            }
        }

        // ---- u = D1 (linear), repack to A frags (m16k32) hi/lo ----
        uint32_t uhi[8], ulo[8];
        #pragma unroll
        for (int s = 0; s < 2; s++) {
            split2(d1[(2*s)*4 + 0], d1[(2*s)*4 + 1], uhi[s*4 + 0], ulo[s*4 + 0]);
            split2(d1[(2*s)*4 + 2], d1[(2*s)*4 + 3], uhi[s*4 + 1], ulo[s*4 + 1]);
            split2(d1[(2*s+1)*4 + 0], d1[(2*s+1)*4 + 1], uhi[s*4 + 2], ulo[s*4 + 2]);
            split2(d1[(2*s+1)*4 + 2], d1[(2*s+1)*4 + 3], uhi[s*4 + 3], ulo[s*4 + 3]);
        }

        // ---- GEMM 2: D2[16,256] = u @ row^T; 32 independent acc chains ----
        float d2[128];
        #pragma unroll
        for (int i = 0; i < 128; i++) d2[i] = 0.0f;
        #pragma unroll
        for (int n = 0; n < 32; n++) {
            #pragma unroll
            for (int s = 0; s < 2; s++) {
                const uint4 bb = __ldg(&pc[(s * 32 + n) * 32 + lane]);  // one LDG.128
                mma16816(&d2[n * 4], &uhi[s * 4], bb.x, bb.y);
                mma16816(&d2[n * 4], &ulo[s * 4], bb.x, bb.y);
                mma16816(&d2[n * 4], &uhi[s * 4], bb.z, bb.w);
            }
        }

        if (blk < 2) {
            // ---- h' = tanh(D2): D-frags ARE next A-frags (hi regs, lo smem) ----
            #pragma unroll
            for (int q = 0; q < 16; q++) {
                uint4 lo;
                split2(tanh_fast(d2[(2*q)*4 + 0]), tanh_fast(d2[(2*q)*4 + 1]),
                       ahi[q*4 + 0], lo.x);
                split2(tanh_fast(d2[(2*q)*4 + 2]), tanh_fast(d2[(2*q)*4 + 3]),
                       ahi[q*4 + 1], lo.y);
                split2(tanh_fast(d2[(2*q+1)*4 + 0]), tanh_fast(d2[(2*q+1)*4 + 1]),
                       ahi[q*4 + 2], lo.z);
                split2(tanh_fast(d2[(2*q+1)*4 + 2]), tanh_fast(d2[(2*q+1)*4 + 3]),
                       ahi[q*4 + 3], lo.w);
                s_alo[q * 128 + tid] = lo;
            }
        } else {
            // ---- fused Phase D: dot with end_w ----
            #pragma unroll
            for (int n = 0; n < 32; n++) {
                const int c0 = 8 * n + 2 * t;
                const float e0 = __ldg(end_w + c0), e1 = __ldg(end_w + c0 + 1);
                s0 = fmaf(tanh_fast(d2[n*4 + 0]), e0, s0);
                s0 = fmaf(tanh_fast(d2[n*4 + 1]), e1, s0);
                s1 = fmaf(tanh_fast(d2[n*4 + 2]), e0, s1);
                s1 = fmaf(tanh_fast(d2[n*4 + 3]), e1, s1);
            }
        }
    }

    // reduce across the 4 lanes of each row group
    s0 += __shfl_xor_sync(0xffffffffu, s0, 1);
    s0 += __shfl_xor_sync(0xffffffffu, s0, 2);
    s1 += __shfl_xor_sync(0xffffffffu, s1, 1);
    s1 += __shfl_xor_sync(0xffffffffu, s1, 2);
    if (t == 0) {
        const float eb = __ldg(end_b);
        out[r0] = s0 + eb;
        out[r1] = s1 + eb;
    }
}

extern "C" void kernel_launch(void* const* d_in, const int* in_sizes, int n_in,
                              void* d_out, int out_size) {
    const float* x  = (const float*)d_in[0];
    const float* t  = (const float*)d_in[1];
    const float* sw = (const float*)d_in[2];
    const float* sb = (const float*)d_in[3];
    const float* ew = (const float*)d_in[4];
    const float* eb = (const float*)d_in[5];
    const float* c0 = (const float*)d_in[6];
    const float* c1 = (const float*)d_in[7];
    const float* c2 = (const float*)d_in[8];
    const float* r0 = (const float*)d_in[9];
    const float* r1 = (const float*)d_in[10];
    const float* r2 = (const float*)d_in[11];
    const float* a0 = (const float*)d_in[12];
    const float* a1 = (const float*)d_in[13];
    const float* a2 = (const float*)d_in[14];
    float* out = (float*)d_out;
    const int N = in_sizes[0];

    pack_kernel<<<(2 * 3 * 64 * 32 + 255) / 256, 256>>>(c0, c1, c2, r0, r1, r2,
                                                        a0, a1, a2);
    pinn_kernel<<<N / 64, 128>>>(x, t, sw, sb, ew, eb, out);
}